// round 16
// baseline (speedup 1.0000x reference)
#include <cuda_runtime.h>

// stepSSM fused kernel, R15: R14 body (2 rows/thread, weight amortization —
// kernel 82.0us, L1 48.7%) with __launch_bounds__(256, 5) to lift occupancy.
//
// R14 profile: L1 49% (slack), issue 30% (slack), occ 43.4% (binding).
// DRAM% tracks warps x outstanding-loads; 5 blocks/SM = 40 warps (+25%)
// at the cost of capping regs at 51 (R14 used 64). Live state is ~52 regs;
// ptxas sheds the excess by rematerializing weight LDS (L1 has headroom)
// rather than spilling the global-loaded state.
//
// Layout unchanged: 4 threads/row, rows r and r+B/2 per thread, both state
// streams fully coalesced float4, scalar broadcast smem consts, quad shfls.
//
// Inputs (metadata order):
//   0: x[B,4]  1: states[4,B,2,4,2]  2: fc1_w[2,4]  3: fc1_b[2]
//   4: fc_w[5,2,2]  5: fc_b[5,2]  6: A[4,2,4,2]  7: Bm[4,2,4,2]
//   8: C[4,1,2,4,2]  9: D[4,1,2]
// Output: h[B,2] ++ new_states[4,B,2,4,2]  (f32)

#define THREADS 256

#define OFF_FC1W 0    // 8
#define OFF_FC1B 8    // 2
#define OFF_FCW  10   // 20
#define OFF_FCB  30   // 10
#define OFF_A    40   // 64
#define OFF_BM   104  // 64
#define OFF_C    168  // 64
#define OFF_D    232  // 8
#define N_CONST  240

__global__ __launch_bounds__(THREADS, 5) void step_ssm_kernel(
    const float4* __restrict__ x,        // [B]
    const float4* __restrict__ states,   // [4*B*4] float4
    const float*  __restrict__ fc1_w,
    const float*  __restrict__ fc1_b,
    const float*  __restrict__ fc_w,
    const float*  __restrict__ fc_b,
    const float*  __restrict__ A,
    const float*  __restrict__ Bm,
    const float*  __restrict__ C,
    const float*  __restrict__ D,
    float2*       __restrict__ out_h,      // [B]
    float4*       __restrict__ out_states, // [4*B*4] float4
    int B)
{
    __shared__ float sc[N_CONST];
    {
        int t = threadIdx.x;
        if (t < N_CONST) {
            float v;
            if      (t < OFF_FC1B) v = fc1_w[t - OFF_FC1W];
            else if (t < OFF_FCW)  v = fc1_b[t - OFF_FC1B];
            else if (t < OFF_FCB)  v = fc_w [t - OFF_FCW];
            else if (t < OFF_A)    v = fc_b [t - OFF_FCB];
            else if (t < OFF_BM)   v = A    [t - OFF_A];
            else if (t < OFF_C)    v = Bm   [t - OFF_BM];
            else if (t < OFF_D)    v = C    [t - OFF_C];
            else                   v = D    [t - OFF_D];
            sc[t] = v;
        }
    }
    __syncthreads();

    const int t    = blockIdx.x * blockDim.x + threadIdx.x;
    const int row  = t >> 2;
    const int q    = t & 3;
    const int half = B >> 1;
    if (row >= half) return;

    const size_t layer_str = (size_t)B * 4;          // float4 units
    const size_t off0      = (size_t)row * 4 + q;    // row r
    const size_t off1      = off0 + (size_t)half * 4;// row r + B/2

    // ---- front-load all global reads (MLP = 10) ----
    float4 s0[4], s1[4];
#pragma unroll
    for (int i = 0; i < 4; i++) {
        s0[i] = __ldcs(states + (size_t)i * layer_str + off0);
        s1[i] = __ldcs(states + (size_t)i * layer_str + off1);
    }
    float4 xv0 = __ldg(x + row);
    float4 xv1 = __ldg(x + row + half);

    // fc1 for both rows (weights read once)
    float a0, a1, a2, a3, a4;
    a0 = sc[OFF_FC1W + 0]; a1 = sc[OFF_FC1W + 1]; a2 = sc[OFF_FC1W + 2];
    a3 = sc[OFF_FC1W + 3]; a4 = sc[OFF_FC1B + 0];
    float h00 = fmaf(xv0.x, a0, fmaf(xv0.y, a1, fmaf(xv0.z, a2, fmaf(xv0.w, a3, a4))));
    float h10 = fmaf(xv1.x, a0, fmaf(xv1.y, a1, fmaf(xv1.z, a2, fmaf(xv1.w, a3, a4))));
    a0 = sc[OFF_FC1W + 4]; a1 = sc[OFF_FC1W + 5]; a2 = sc[OFF_FC1W + 6];
    a3 = sc[OFF_FC1W + 7]; a4 = sc[OFF_FC1B + 1];
    float h01 = fmaf(xv0.x, a0, fmaf(xv0.y, a1, fmaf(xv0.z, a2, fmaf(xv0.w, a3, a4))));
    float h11 = fmaf(xv1.x, a0, fmaf(xv1.y, a1, fmaf(xv1.z, a2, fmaf(xv1.w, a3, a4))));

    const int hd = q >> 1;
    const int kq = q * 4;

#pragma unroll
    for (int i = 0; i < 4; i++) {
        const int lb = i * 16 + kq;

        // layer constants read once, used for both rows
        float Ar0 = sc[OFF_A  + lb + 0], Ai0 = sc[OFF_A  + lb + 1];
        float Ar1 = sc[OFF_A  + lb + 2], Ai1 = sc[OFF_A  + lb + 3];
        float Br0 = sc[OFF_BM + lb + 0], Bi0 = sc[OFF_BM + lb + 1];
        float Br1 = sc[OFF_BM + lb + 2], Bi1 = sc[OFF_BM + lb + 3];
        float Cr0 = sc[OFF_C  + lb + 0], Ci0 = sc[OFF_C  + lb + 1];
        float Cr1 = sc[OFF_C  + lb + 2], Ci1 = sc[OFF_C  + lb + 3];
        float dd  = sc[OFF_D + i * 2 + hd];

        const float u0 = (hd == 0) ? h00 : h01;
        const float u1 = (hd == 0) ? h10 : h11;

        // row 0 state update + store
        float nr00 = fmaf(Ar0, s0[i].x, fmaf(-Ai0, s0[i].y, Br0 * u0));
        float ni00 = fmaf(Ar0, s0[i].y, fmaf( Ai0, s0[i].x, Bi0 * u0));
        float nr01 = fmaf(Ar1, s0[i].z, fmaf(-Ai1, s0[i].w, Br1 * u0));
        float ni01 = fmaf(Ar1, s0[i].w, fmaf( Ai1, s0[i].z, Bi1 * u0));
        __stcs(out_states + (size_t)i * layer_str + off0,
               make_float4(nr00, ni00, nr01, ni01));

        // row 1 state update + store
        float nr10 = fmaf(Ar0, s1[i].x, fmaf(-Ai0, s1[i].y, Br0 * u1));
        float ni10 = fmaf(Ar0, s1[i].y, fmaf( Ai0, s1[i].x, Bi0 * u1));
        float nr11 = fmaf(Ar1, s1[i].z, fmaf(-Ai1, s1[i].w, Br1 * u1));
        float ni11 = fmaf(Ar1, s1[i].w, fmaf( Ai1, s1[i].z, Bi1 * u1));
        __stcs(out_states + (size_t)i * layer_str + off1,
               make_float4(nr10, ni10, nr11, ni11));

        // C-projections, quad reductions (per row), head swap
        float ac0 = fmaf(Cr0, nr00, fmaf(-Ci0, ni00, fmaf(Cr1, nr01, -Ci1 * ni01)));
        float ac1 = fmaf(Cr0, nr10, fmaf(-Ci0, ni10, fmaf(Cr1, nr11, -Ci1 * ni11)));
        ac0 += __shfl_xor_sync(0xFFFFFFFFu, ac0, 1);
        ac1 += __shfl_xor_sync(0xFFFFFFFFu, ac1, 1);

        float yA = fmaf(2.0f, ac0, u0 * dd);
        float yB = fmaf(2.0f, ac1, u1 * dd);
        yA = (yA >= 0.0f) ? yA : 0.125f * yA;
        yB = (yB >= 0.0f) ? yB : 0.125f * yB;
        float yAo = __shfl_xor_sync(0xFFFFFFFFu, yA, 2);
        float yBo = __shfl_xor_sync(0xFFFFFFFFu, yB, 2);
        float y00 = (hd == 0) ? yA  : yAo;   // row0 head0
        float y01 = (hd == 0) ? yAo : yA;    // row0 head1
        float y10 = (hd == 0) ? yB  : yBo;
        float y11 = (hd == 0) ? yBo : yB;

        // fc_i (weights read once, applied to both rows)
        const int wb = OFF_FCW + i * 4;
        float w0 = sc[wb + 0], w1 = sc[wb + 1], w2 = sc[wb + 2], w3 = sc[wb + 3];
        float f0 = sc[OFF_FCB + i * 2 + 0], f1 = sc[OFF_FCB + i * 2 + 1];
        h00 = fmaf(y00, w0, fmaf(y01, w1, f0));
        h01 = fmaf(y00, w2, fmaf(y01, w3, f1));
        h10 = fmaf(y10, w0, fmaf(y11, w1, f0));
        h11 = fmaf(y10, w2, fmaf(y11, w3, f1));
    }

    // fc10 for both rows — lane q==0 writes contiguous float2s
    if (q == 0) {
        const int wb = OFF_FCW + 16;
        float w0 = sc[wb + 0], w1 = sc[wb + 1], w2 = sc[wb + 2], w3 = sc[wb + 3];
        float f0 = sc[OFF_FCB + 8], f1 = sc[OFF_FCB + 9];
        out_h[row]        = make_float2(fmaf(h00, w0, fmaf(h01, w1, f0)),
                                        fmaf(h00, w2, fmaf(h01, w3, f1)));
        out_h[row + half] = make_float2(fmaf(h10, w0, fmaf(h11, w1, f0)),
                                        fmaf(h10, w2, fmaf(h11, w3, f1)));
    }
}

extern "C" void kernel_launch(void* const* d_in, const int* in_sizes, int n_in,
                              void* d_out, int out_size)
{
    const float* x     = (const float*)d_in[0];
    const float* states= (const float*)d_in[1];
    const float* fc1_w = (const float*)d_in[2];
    const float* fc1_b = (const float*)d_in[3];
    const float* fc_w  = (const float*)d_in[4];
    const float* fc_b  = (const float*)d_in[5];
    const float* A     = (const float*)d_in[6];
    const float* Bm    = (const float*)d_in[7];
    const float* C     = (const float*)d_in[8];
    const float* D     = (const float*)d_in[9];

    int B = in_sizes[0] / 4;  // x is [B,4]

    float*  out = (float*)d_out;
    float2* oh  = (float2*)out;                   // h: [B,2]
    float4* ost = (float4*)(out + (size_t)2 * B); // new_states: [4,B,2,4,2]

    long long total = ((long long)B / 2) * 4;     // 4 threads per row-pair
    int grid = (int)((total + THREADS - 1) / THREADS);
    step_ssm_kernel<<<grid, THREADS>>>(
        (const float4*)x, (const float4*)states,
        fc1_w, fc1_b, fc_w, fc_b, A, Bm, C, D,
        oh, ost, B);
}

// round 17
// speedup vs baseline: 1.0680x; 1.0680x over previous
#include <cuda_runtime.h>

// stepSSM fused kernel, R16: 2 rows/thread + depth-2 software pipeline of the
// state loads, so the register live-set genuinely fits 5 blocks/SM.
//
// R14 (front-load all 4 layers): 64 regs -> 4 blocks, occ 43%, kernel 82.0.
// R15 (same body forced to 48 regs): ptxas spilled STATE to local (L2 49%),
// DRAM 74% -> 92us. Fix: shrink the real live set instead of squeezing —
// hold only 2 layers of state (4 float4 = 16 regs): load L0,L1 up front,
// prefetch L(i+2) right after computing layer i. Natural need ~48 regs, so
// __launch_bounds__(256,5) (cap 51) holds WITHOUT spills; 40 warps/SM.
// Latency: layer compute ~150cyc vs DRAM ~400cyc; 10 warps/SMSP cover the
// 150/400 duty cycle with 4x margin; outstanding bytes/SM ~40KB >> ~11KB
// needed for HBM saturation.
//
// Layout (proven): 4 threads/row, rows r and r+B/2 per thread, coalesced
// float4 state streams, scalar broadcast smem consts (amortized over 2 rows),
// quad shfl reductions.
//
// Inputs (metadata order):
//   0: x[B,4]  1: states[4,B,2,4,2]  2: fc1_w[2,4]  3: fc1_b[2]
//   4: fc_w[5,2,2]  5: fc_b[5,2]  6: A[4,2,4,2]  7: Bm[4,2,4,2]
//   8: C[4,1,2,4,2]  9: D[4,1,2]
// Output: h[B,2] ++ new_states[4,B,2,4,2]  (f32)

#define THREADS 256

#define OFF_FC1W 0    // 8
#define OFF_FC1B 8    // 2
#define OFF_FCW  10   // 20
#define OFF_FCB  30   // 10
#define OFF_A    40   // 64
#define OFF_BM   104  // 64
#define OFF_C    168  // 64
#define OFF_D    232  // 8
#define N_CONST  240

// One SSM layer for both rows. i must be a literal (forceinline + constant fold).
__device__ __forceinline__ void layer_step(
    const float sc[N_CONST], int i, int hd, int kq,
    const float4& s0, const float4& s1,
    float& h00, float& h01, float& h10, float& h11,
    float4* __restrict__ out_states, size_t layer_str, size_t off0, size_t off1)
{
    const int lb = i * 16 + kq;

    float Ar0 = sc[OFF_A  + lb + 0], Ai0 = sc[OFF_A  + lb + 1];
    float Ar1 = sc[OFF_A  + lb + 2], Ai1 = sc[OFF_A  + lb + 3];
    float Br0 = sc[OFF_BM + lb + 0], Bi0 = sc[OFF_BM + lb + 1];
    float Br1 = sc[OFF_BM + lb + 2], Bi1 = sc[OFF_BM + lb + 3];
    float Cr0 = sc[OFF_C  + lb + 0], Ci0 = sc[OFF_C  + lb + 1];
    float Cr1 = sc[OFF_C  + lb + 2], Ci1 = sc[OFF_C  + lb + 3];
    float dd  = sc[OFF_D + i * 2 + hd];

    const float u0 = (hd == 0) ? h00 : h01;
    const float u1 = (hd == 0) ? h10 : h11;

    float nr00 = fmaf(Ar0, s0.x, fmaf(-Ai0, s0.y, Br0 * u0));
    float ni00 = fmaf(Ar0, s0.y, fmaf( Ai0, s0.x, Bi0 * u0));
    float nr01 = fmaf(Ar1, s0.z, fmaf(-Ai1, s0.w, Br1 * u0));
    float ni01 = fmaf(Ar1, s0.w, fmaf( Ai1, s0.z, Bi1 * u0));
    __stcs(out_states + (size_t)i * layer_str + off0,
           make_float4(nr00, ni00, nr01, ni01));

    float nr10 = fmaf(Ar0, s1.x, fmaf(-Ai0, s1.y, Br0 * u1));
    float ni10 = fmaf(Ar0, s1.y, fmaf( Ai0, s1.x, Bi0 * u1));
    float nr11 = fmaf(Ar1, s1.z, fmaf(-Ai1, s1.w, Br1 * u1));
    float ni11 = fmaf(Ar1, s1.w, fmaf( Ai1, s1.z, Bi1 * u1));
    __stcs(out_states + (size_t)i * layer_str + off1,
           make_float4(nr10, ni10, nr11, ni11));

    float ac0 = fmaf(Cr0, nr00, fmaf(-Ci0, ni00, fmaf(Cr1, nr01, -Ci1 * ni01)));
    float ac1 = fmaf(Cr0, nr10, fmaf(-Ci0, ni10, fmaf(Cr1, nr11, -Ci1 * ni11)));
    ac0 += __shfl_xor_sync(0xFFFFFFFFu, ac0, 1);
    ac1 += __shfl_xor_sync(0xFFFFFFFFu, ac1, 1);

    float yA = fmaf(2.0f, ac0, u0 * dd);
    float yB = fmaf(2.0f, ac1, u1 * dd);
    yA = (yA >= 0.0f) ? yA : 0.125f * yA;
    yB = (yB >= 0.0f) ? yB : 0.125f * yB;
    float yAo = __shfl_xor_sync(0xFFFFFFFFu, yA, 2);
    float yBo = __shfl_xor_sync(0xFFFFFFFFu, yB, 2);
    float y00 = (hd == 0) ? yA  : yAo;
    float y01 = (hd == 0) ? yAo : yA;
    float y10 = (hd == 0) ? yB  : yBo;
    float y11 = (hd == 0) ? yBo : yB;

    const int wb = OFF_FCW + i * 4;
    float w0 = sc[wb + 0], w1 = sc[wb + 1], w2 = sc[wb + 2], w3 = sc[wb + 3];
    float f0 = sc[OFF_FCB + i * 2 + 0], f1 = sc[OFF_FCB + i * 2 + 1];
    h00 = fmaf(y00, w0, fmaf(y01, w1, f0));
    h01 = fmaf(y00, w2, fmaf(y01, w3, f1));
    h10 = fmaf(y10, w0, fmaf(y11, w1, f0));
    h11 = fmaf(y10, w2, fmaf(y11, w3, f1));
}

__global__ __launch_bounds__(THREADS, 5) void step_ssm_kernel(
    const float4* __restrict__ x,        // [B]
    const float4* __restrict__ states,   // [4*B*4] float4
    const float*  __restrict__ fc1_w,
    const float*  __restrict__ fc1_b,
    const float*  __restrict__ fc_w,
    const float*  __restrict__ fc_b,
    const float*  __restrict__ A,
    const float*  __restrict__ Bm,
    const float*  __restrict__ C,
    const float*  __restrict__ D,
    float2*       __restrict__ out_h,      // [B]
    float4*       __restrict__ out_states, // [4*B*4] float4
    int B)
{
    __shared__ float sc[N_CONST];
    {
        int t = threadIdx.x;
        if (t < N_CONST) {
            float v;
            if      (t < OFF_FC1B) v = fc1_w[t - OFF_FC1W];
            else if (t < OFF_FCW)  v = fc1_b[t - OFF_FC1B];
            else if (t < OFF_FCB)  v = fc_w [t - OFF_FCW];
            else if (t < OFF_A)    v = fc_b [t - OFF_FCB];
            else if (t < OFF_BM)   v = A    [t - OFF_A];
            else if (t < OFF_C)    v = Bm   [t - OFF_BM];
            else if (t < OFF_D)    v = C    [t - OFF_C];
            else                   v = D    [t - OFF_D];
            sc[t] = v;
        }
    }
    __syncthreads();

    const int t    = blockIdx.x * blockDim.x + threadIdx.x;
    const int row  = t >> 2;
    const int q    = t & 3;
    const int half = B >> 1;
    if (row >= half) return;

    const size_t layer_str = (size_t)B * 4;           // float4 units
    const size_t off0      = (size_t)row * 4 + q;     // row r
    const size_t off1      = off0 + (size_t)half * 4; // row r + B/2

    // pipeline prologue: layers 0 and 1 in flight (4 float4 live)
    float4 sa0 = __ldcs(states + off0);
    float4 sa1 = __ldcs(states + off1);
    float4 sb0 = __ldcs(states + layer_str + off0);
    float4 sb1 = __ldcs(states + layer_str + off1);
    float4 xv0 = __ldg(x + row);
    float4 xv1 = __ldg(x + row + half);

    // fc1 for both rows (weights read once)
    float a0, a1, a2, a3, a4;
    a0 = sc[OFF_FC1W + 0]; a1 = sc[OFF_FC1W + 1]; a2 = sc[OFF_FC1W + 2];
    a3 = sc[OFF_FC1W + 3]; a4 = sc[OFF_FC1B + 0];
    float h00 = fmaf(xv0.x, a0, fmaf(xv0.y, a1, fmaf(xv0.z, a2, fmaf(xv0.w, a3, a4))));
    float h10 = fmaf(xv1.x, a0, fmaf(xv1.y, a1, fmaf(xv1.z, a2, fmaf(xv1.w, a3, a4))));
    a0 = sc[OFF_FC1W + 4]; a1 = sc[OFF_FC1W + 5]; a2 = sc[OFF_FC1W + 6];
    a3 = sc[OFF_FC1W + 7]; a4 = sc[OFF_FC1B + 1];
    float h01 = fmaf(xv0.x, a0, fmaf(xv0.y, a1, fmaf(xv0.z, a2, fmaf(xv0.w, a3, a4))));
    float h11 = fmaf(xv1.x, a0, fmaf(xv1.y, a1, fmaf(xv1.z, a2, fmaf(xv1.w, a3, a4))));

    const int hd = q >> 1;
    const int kq = q * 4;

    // layer 0, then prefetch layer 2 into the freed A-buffer
    layer_step(sc, 0, hd, kq, sa0, sa1, h00, h01, h10, h11,
               out_states, layer_str, off0, off1);
    sa0 = __ldcs(states + 2 * layer_str + off0);
    sa1 = __ldcs(states + 2 * layer_str + off1);

    // layer 1, then prefetch layer 3 into the freed B-buffer
    layer_step(sc, 1, hd, kq, sb0, sb1, h00, h01, h10, h11,
               out_states, layer_str, off0, off1);
    sb0 = __ldcs(states + 3 * layer_str + off0);
    sb1 = __ldcs(states + 3 * layer_str + off1);

    // layers 2 and 3
    layer_step(sc, 2, hd, kq, sa0, sa1, h00, h01, h10, h11,
               out_states, layer_str, off0, off1);
    layer_step(sc, 3, hd, kq, sb0, sb1, h00, h01, h10, h11,
               out_states, layer_str, off0, off1);

    // fc10 for both rows — lane q==0 writes contiguous float2s
    if (q == 0) {
        const int wb = OFF_FCW + 16;
        float w0 = sc[wb + 0], w1 = sc[wb + 1], w2 = sc[wb + 2], w3 = sc[wb + 3];
        float f0 = sc[OFF_FCB + 8], f1 = sc[OFF_FCB + 9];
        out_h[row]        = make_float2(fmaf(h00, w0, fmaf(h01, w1, f0)),
                                        fmaf(h00, w2, fmaf(h01, w3, f1)));
        out_h[row + half] = make_float2(fmaf(h10, w0, fmaf(h11, w1, f0)),
                                        fmaf(h10, w2, fmaf(h11, w3, f1)));
    }
}

extern "C" void kernel_launch(void* const* d_in, const int* in_sizes, int n_in,
                              void* d_out, int out_size)
{
    const float* x     = (const float*)d_in[0];
    const float* states= (const float*)d_in[1];
    const float* fc1_w = (const float*)d_in[2];
    const float* fc1_b = (const float*)d_in[3];
    const float* fc_w  = (const float*)d_in[4];
    const float* fc_b  = (const float*)d_in[5];
    const float* A     = (const float*)d_in[6];
    const float* Bm    = (const float*)d_in[7];
    const float* C     = (const float*)d_in[8];
    const float* D     = (const float*)d_in[9];

    int B = in_sizes[0] / 4;  // x is [B,4]

    float*  out = (float*)d_out;
    float2* oh  = (float2*)out;                   // h: [B,2]
    float4* ost = (float4*)(out + (size_t)2 * B); // new_states: [4,B,2,4,2]

    long long total = ((long long)B / 2) * 4;     // 4 threads per row-pair
    int grid = (int)((total + THREADS - 1) / THREADS);
    step_ssm_kernel<<<grid, THREADS>>>(
        (const float4*)x, (const float4*)states,
        fc1_w, fc1_b, fc_w, fc_b, A, Bm, C, D,
        oh, ost, B);
}